// round 9
// baseline (speedup 1.0000x reference)
#include <cuda_runtime.h>
#include <cuda_bf16.h>
#include <cstdint>

#define BB    4
#define LQ    256
#define LK    2048
#define HIDD  1024
#define NH    16
#define DD    64
#define QT    16                     /* q rows per CTA */
#define NT    256                    /* threads per CTA */
#define NCH   32                     /* k-chunks */
#define CK    64                     /* k rows per chunk */

#define CENTER_C      72.21632f
#define INV_SCALING_C 0.14662718f

typedef unsigned long long u64;
#define ABSM 0x7FFFFFFF7FFFFFFFULL

__device__ float g_VT[(size_t)BB * NH * DD * LK];   // V transposed [b,h,d,k]

__device__ __forceinline__ u64 fadd2(u64 a, u64 b) {
    u64 r; asm("add.rn.f32x2 %0, %1, %2;" : "=l"(r) : "l"(a), "l"(b)); return r;
}
__device__ __forceinline__ u64 ffma2(u64 a, u64 b, u64 c) {
    u64 r; asm("fma.rn.f32x2 %0, %1, %2, %3;" : "=l"(r) : "l"(a), "l"(b), "l"(c)); return r;
}
__device__ __forceinline__ float2 upk2(u64 a) {
    float2 f; asm("mov.b64 {%0, %1}, %2;" : "=f"(f.x), "=f"(f.y) : "l"(a)); return f;
}
__device__ __forceinline__ void cp16(uint32_t dst, const void* src) {
    asm volatile("cp.async.cg.shared.global [%0], [%1], 16;" :: "r"(dst), "l"(src));
}

// ---------------------------------------------------------------------------
// Kernel 0: transpose V -> VT[b,h,d,k].
// ---------------------------------------------------------------------------
__global__ __launch_bounds__(256) void k_vtrans(const float* __restrict__ Vg)
{
    __shared__ float t[64][65];
    const int bh = blockIdx.y, b = bh >> 4, h = bh & 15;
    const int k0 = blockIdx.x * 64;
    const int tid = threadIdx.x;
    #pragma unroll
    for (int r = 0; r < 4; r++) {
        int i = tid + 256 * r; int kr = i >> 4, g = i & 15;
        float4 v = *(const float4*)(Vg + ((size_t)(b * LK + k0 + kr)) * HIDD + h * DD + 4 * g);
        t[kr][4 * g + 0] = v.x; t[kr][4 * g + 1] = v.y;
        t[kr][4 * g + 2] = v.z; t[kr][4 * g + 3] = v.w;
    }
    __syncthreads();
    #pragma unroll
    for (int r = 0; r < 4; r++) {
        int i = tid + 256 * r; int d = i >> 4, g = i & 15;
        float4 o = make_float4(t[4 * g + 0][d], t[4 * g + 1][d], t[4 * g + 2][d], t[4 * g + 3][d]);
        *(float4*)(g_VT + ((size_t)(bh * DD + d)) * LK + k0 + 4 * g) = o;
    }
}

// ---------------------------------------------------------------------------
// Fused kernel. grid (LQ/16, NH, BB), block 256 (8 warps), ~45.5KB smem
//  -> 3 CTAs/SM (6 warps/SMSP). 64-row K/V chunks, 32 chunks.
// Phase 1: warp = kgx (w&1: 32 k lanes) x qg (w>>1: 4 q rows); K rows in regs;
//   e written unnormalized to attn (L2-hot); sums in regs.
// Phase 2: warp = kg2 (w&1: 32 k) x qg2 (4 q); streams V^T + e chunks.
//   SMEM floats: [0,8192)       K / V^T ring (2 x 4096)
//                [8192,10240)   e-stage ring (2 x 1024)
//                [10240,11264)  qbuf (negated Q)
//                [11264,11328)  dbuf  [11328,11344) invs  [11344,11376) part
// ---------------------------------------------------------------------------
__global__ __launch_bounds__(NT, 3) void k_fused(
    const float* __restrict__ Qg, const float* __restrict__ Kg,
    const float* __restrict__ diag,
    float* __restrict__ attn, float* __restrict__ out0)
{
    extern __shared__ float smem[];
    float* estg0 = smem + 8192;
    float* qbuf  = smem + 10240;
    float* dbuf  = smem + 11264;
    float* invs  = smem + 11328;
    float* part  = smem + 11344;

    const int b  = blockIdx.z, h = blockIdx.y;
    const int q0 = blockIdx.x * QT;
    const int tid = threadIdx.x, w = tid >> 5, lane = tid & 31;
    const int kgx = w & 1, qg = w >> 1;         // phase-1: k-half (32k), 4 q rows
    const int s  = lane & 7;
    const uint32_t sbase = (uint32_t)__cvta_generic_to_shared(smem);
    const uint32_t estg_b = sbase + 8192u * 4u;

    const size_t arow0 = (((size_t)(b * NH + h)) * LQ + q0) * (size_t)LK;

    // ---- prologue --------------------------------------------------------
    if (tid < 16)
        ((float4*)dbuf)[tid] = ((const float4*)(diag + h * DD))[tid];
    {
        int qr = tid >> 4, g = tid & 15;        // 16 rows x 16 f4, negated
        float4 v = ((const float4*)(Qg + ((size_t)(b * LQ + q0 + qr)) * HIDD + h * DD))[g];
        ((float4*)qbuf)[qr * 16 + g] = make_float4(-v.x, -v.y, -v.z, -v.w);
    }

    // prefetch K chunk 0 (XOR-swizzled f4 rows: 64 k-rows x 16 f4)
    #pragma unroll
    for (int r = 0; r < 4; r++) {
        int i = tid + NT * r; int kr = i >> 4, g = i & 15;
        cp16(sbase + (uint32_t)((kr * 16 + (g ^ (kr & 7))) * 16),
             ((const float4*)(Kg + ((size_t)(b * LK + kr)) * HIDD + h * DD)) + g);
    }
    asm volatile("cp.async.commit_group;");

    const ulonglong2* qb2 = (const ulonglong2*)qbuf;
    const ulonglong2* db2 = (const ulonglong2*)dbuf;
    float sume[4] = {0.f, 0.f, 0.f, 0.f};
    const int krow16 = (kgx * 32 + lane) * 16;

    // ==== Phase 1: one barrier per chunk; e -> gmem (unnormalized) ========
    for (int c = 0; c < NCH; c++) {
        asm volatile("cp.async.wait_group 0;");
        __syncthreads();          // buf[c&1] full; everyone done with buf[(c+1)&1]

        if (c + 1 < NCH) {        // prefetch next chunk into the other buffer
            uint32_t boff = (uint32_t)(((c + 1) & 1) * 16384);
            #pragma unroll
            for (int r = 0; r < 4; r++) {
                int i = tid + NT * r; int kr = i >> 4, g = i & 15;
                cp16(sbase + boff + (uint32_t)((kr * 16 + (g ^ (kr & 7))) * 16),
                     ((const float4*)(Kg + ((size_t)(b * LK + (c + 1) * CK + kr)) * HIDD
                                      + h * DD)) + g);
            }
            asm volatile("cp.async.commit_group;");
        }

        // pull this warp's K rows into registers (64 floats per lane)
        const ulonglong2* kb2 = (const ulonglong2*)(smem + (c & 1) * 4096);
        ulonglong2 kvr[16];
        #pragma unroll
        for (int g = 0; g < 16; g++) kvr[g] = kb2[krow16 + (g ^ s)];

        u64 acc[4];
        #pragma unroll
        for (int q = 0; q < 4; q++) acc[q] = 0ull;

        #pragma unroll
        for (int g = 0; g < 16; g++) {
            ulonglong2 dv = db2[g];                              // broadcast
            #pragma unroll
            for (int q = 0; q < 4; q++) {
                ulonglong2 qv = qb2[(qg * 4 + q) * 16 + g];      // broadcast
                u64 t0 = fadd2(kvr[g].x, qv.x) & ABSM;  // |k - q| (q pre-negated)
                u64 t1 = fadd2(kvr[g].y, qv.y) & ABSM;
                acc[q] = ffma2(dv.x, t0, acc[q]);
                acc[q] = ffma2(dv.y, t1, acc[q]);
            }
        }

        #pragma unroll
        for (int q = 0; q < 4; q++) {
            float2 a = upk2(acc[q]);
            float e = __expf((CENTER_C - (a.x + a.y)) * INV_SCALING_C);
            attn[arow0 + (size_t)(qg * 4 + q) * LK + c * CK + kgx * 32 + lane] = e;
            sume[q] += e;
        }
    }

    // softmax partial sums per (q, kgx)
    #pragma unroll
    for (int q = 0; q < 4; q++) {
        float ssum = sume[q];
        #pragma unroll
        for (int o = 16; o > 0; o >>= 1) ssum += __shfl_xor_sync(0xffffffffu, ssum, o);
        if (lane == 0) part[(qg * 4 + q) * 2 + kgx] = ssum;
    }
    __syncthreads();   // e STGs + parts visible block-wide
    if (tid < 16)
        invs[tid] = 1.f / (part[tid * 2] + part[tid * 2 + 1]);

    // prefetch V^T chunk 0 + e chunk 0
    const float* vtb = g_VT + ((size_t)(b * NH + h)) * DD * LK;
    #pragma unroll
    for (int r = 0; r < 4; r++) {
        int j = tid + NT * r; int d = j >> 4, k4 = j & 15;
        cp16(sbase + (uint32_t)((d * 16 + (k4 ^ (d & 7))) * 16),
             vtb + (size_t)d * LK + 4 * k4);
    }
    {
        int qq = tid >> 4, k4 = tid & 15;
        cp16(estg_b + (uint32_t)(tid * 16),
             attn + arow0 + (size_t)qq * LK + 4 * k4);
    }
    asm volatile("cp.async.commit_group;");

    // ==== Phase 2: p write + P@V ==========================================
    const int kg2 = w & 1, qg2 = w >> 1;
    u64 acc2[4][2];
    #pragma unroll
    for (int q = 0; q < 4; q++) { acc2[q][0] = 0ull; acc2[q][1] = 0ull; }

    for (int c = 0; c < NCH; c++) {
        int kc = c * CK;
        asm volatile("cp.async.wait_group 0;");
        __syncthreads();   // buf/estg[c&1] full; also publishes invs on c==0

        if (c + 1 < NCH) {
            uint32_t boff  = (uint32_t)(((c + 1) & 1) * 16384);
            uint32_t boffe = (uint32_t)(((c + 1) & 1) * 4096);
            #pragma unroll
            for (int r = 0; r < 4; r++) {
                int j = tid + NT * r; int d = j >> 4, k4 = j & 15;
                cp16(sbase + boff + (uint32_t)((d * 16 + (k4 ^ (d & 7))) * 16),
                     vtb + (size_t)d * LK + kc + CK + 4 * k4);
            }
            {
                int qq = tid >> 4, k4 = tid & 15;
                cp16(estg_b + boffe + (uint32_t)(tid * 16),
                     attn + arow0 + (size_t)qq * LK + kc + CK + 4 * k4);
            }
            asm volatile("cp.async.commit_group;");
        }

        const float* estg = estg0 + (c & 1) * 1024;

        // write p = e * inv (read stage, coalesced STG.128): 1 f4 per thread
        {
            int qq = tid >> 4, k4 = tid & 15;
            float4 e4 = *(const float4*)(estg + tid * 4);
            float iv = invs[qq];
            float4 p = make_float4(e4.x * iv, e4.y * iv, e4.z * iv, e4.w * iv);
            *(float4*)(attn + arow0 + (size_t)qq * LK + kc + 4 * k4) = p;
        }

        // P@V: warp covers k-half (8 f4), 4 q rows; lane = d (two halves)
        const float4* vb4 = ((const float4*)smem) + (c & 1) * 1024;
        #pragma unroll
        for (int k4i = 0; k4i < 8; k4i++) {
            int kidx4 = kg2 * 8 + k4i;
            int sw = kidx4 ^ s;
            ulonglong2 v0 = *(const ulonglong2*)&vb4[lane * 16 + sw];
            ulonglong2 v1 = *(const ulonglong2*)&vb4[(lane + 32) * 16 + sw];
            #pragma unroll
            for (int q = 0; q < 4; q++) {
                ulonglong2 pp = *(const ulonglong2*)(estg + (qg2 * 4 + q) * 64
                                                     + kidx4 * 4);   // broadcast
                acc2[q][0] = ffma2(pp.x, v0.x, acc2[q][0]);
                acc2[q][0] = ffma2(pp.y, v0.y, acc2[q][0]);
                acc2[q][1] = ffma2(pp.x, v1.x, acc2[q][1]);
                acc2[q][1] = ffma2(pp.y, v1.y, acc2[q][1]);
            }
        }
    }

    // reduce k-half partials: red[2][16q][64d] in ring buffer 0 area
    // (last chunk c=31 used buffer 1; buffer 0 free since iter-31 barrier)
    float* red = smem;
    #pragma unroll
    for (int q = 0; q < 4; q++) {
        float2 a0 = upk2(acc2[q][0]);
        float2 a1 = upk2(acc2[q][1]);
        red[kg2 * 1024 + (qg2 * 4 + q) * 64 + lane]      = a0.x + a0.y;
        red[kg2 * 1024 + (qg2 * 4 + q) * 64 + 32 + lane] = a1.x + a1.y;
    }
    __syncthreads();
    #pragma unroll
    for (int r = 0; r < 4; r++) {
        int j = tid + NT * r;                   // j = qq*64 + d
        int qq = j >> 6, d = j & 63;
        float v = red[j] + red[1024 + j];
        out0[((size_t)(b * LQ + q0 + qq)) * HIDD + h * DD + d] = v * invs[qq];
    }
}

#define SMEMF (11376 * 4)    /* 45504 B -> 3 CTAs/SM */

extern "C" void kernel_launch(void* const* d_in, const int* in_sizes, int n_in,
                              void* d_out, int out_size)
{
    const float* Qg = (const float*)d_in[0];
    const float* Kg = (const float*)d_in[1];
    const float* Vg = (const float*)d_in[2];
    const float* dg = (const float*)d_in[3];

    float* out0 = (float*)d_out;
    float* attn = out0 + (size_t)BB * LQ * HIDD;   // (output, attention) concat

    cudaFuncSetAttribute(k_fused, cudaFuncAttributeMaxDynamicSharedMemorySize, SMEMF);

    k_vtrans<<<dim3(LK / 64, BB * NH), 256>>>(Vg);
    k_fused<<<dim3(LQ / QT, NH, BB), NT, SMEMF>>>(Qg, Kg, dg, attn, out0);
}